// round 8
// baseline (speedup 1.0000x reference)
#include <cuda_runtime.h>

// FMFMNeuronInhib: T=1024 LIF steps over B=16384 neurons. HBM stream.
// R8: identical algorithm to R7 (4 balanced chunks, WARM=192, depth-2
// U=8 register prefetch, evict_last policy on warm-up loads, streaming
// main loads/stores) with TPB 128->256. Rationale: R7 hit minimal traffic
// (246MB) but only 5.6/8 TB/s. 512 blocks x 3 streams = 1536 concurrent
// HBM streams in 0.5-1KB bursts -> poor row locality. TPB=256 doubles
// per-stream burst size (2KB read, 1KB store) and halves stream count;
// also 16 warps/SM (2 blocks/SM, all 256 blocks resident, regs<=128).

#define T_STEPS 1024
#define BATCH   16384
#define NCHUNK  4
#define WARM    192
#define L_TAIL  208                                  // stored, chunks 1..3
#define L_HEAD  (T_STEPS - (NCHUNK - 1) * L_TAIL)    // 400, chunk 0
#define U       8
#define TPB     256
#define STRIDE  ((size_t)BATCH)

// evict_last access policy (fraction 1.0)
__device__ __forceinline__ unsigned long long make_keep_policy() {
    unsigned long long pol;
    asm("createpolicy.fractional.L2::evict_last.b64 %0, 1.0;" : "=l"(pol));
    return pol;
}

// First-of-two-readers load: keep in L2 until the trailing reader arrives.
__device__ __forceinline__ float2 ldg_keep(const float2* p, unsigned long long pol) {
    float2 v;
    asm("ld.global.nc.L2::cache_hint.v2.f32 {%0,%1}, [%2], %3;"
        : "=f"(v.x), "=f"(v.y) : "l"(p), "l"(pol));
    return v;
}

template <bool STORE, bool PREFETCH, bool KEEP>
__device__ __forceinline__ void win(
    float2* __restrict__ buf,        // consumed; refilled from `pre` if PREFETCH
    const float2* __restrict__ pre,  // absolute src of window t+2U
    unsigned long long pol,
    float& mem, float& inh,
    float w0, float w1, float wi,
    float* __restrict__ spk, float* __restrict__ memo, int tbase)
{
#pragma unroll
    for (int u = 0; u < U; u++) {
        const float2 v = buf[u];
        if (PREFETCH)
            buf[u] = KEEP ? ldg_keep(pre + (size_t)u * STRIDE, pol)
                          : __ldcs(pre + (size_t)u * STRIDE);

        // inh = 0.6*inh + x0
        inh = fmaf(0.6f, inh, v.x);
        // cur = 0.7*x0 + 1.0*x1 + w_inh*inh
        float cur = fmaf(w0, v.x, w1 * v.y);
        cur = fmaf(wi, inh, cur);
        // reset from OLD mem (threshold 1), then mem = 0.9*mem + cur - reset
        const float reset = (mem > 1.0f) ? 1.0f : 0.0f;
        mem = fmaf(0.9f, mem, cur - reset);

        if (STORE) {
            const float s = (mem > 1.0f) ? 1.0f : 0.0f;
            __stcs(spk  + (size_t)(tbase + u) * STRIDE, s);
            __stcs(memo + (size_t)(tbase + u) * STRIDE, mem);
        }
    }
}

__global__ void __launch_bounds__(TPB, 1) fmfm_kernel(
    const float2* __restrict__ x,      // [T, B] pairs (x0, x1)
    const float*  __restrict__ w_exc,  // [2] = {0.7, 1.0}
    const float*  __restrict__ w_inh,  // [1] = {-1.0}
    float*        __restrict__ out)    // [2, T, B]: spk_rec then mem_rec
{
    const int nb    = BATCH / TPB;                 // blocks per chunk
    const int chunk = blockIdx.x / nb;
    const int b     = (blockIdx.x % nb) * TPB + threadIdx.x;

    const float w0 = __ldg(&w_exc[0]);
    const float w1 = __ldg(&w_exc[1]);
    const float wi = __ldg(&w_inh[0]);

    const unsigned long long pol = make_keep_policy();

    // Chunk 0: store [0, 400), no warm-up (400 steps total).
    // Chunk i>=1: store [400 + (i-1)*208, +208), warm-up 192 (400 steps total).
    const int cs = (chunk == 0) ? 0 : L_HEAD + (chunk - 1) * L_TAIL;
    const int ce = (chunk == 0) ? L_HEAD : cs + L_TAIL;
    const int t0 = (chunk == 0) ? 0 : cs - WARM;

    const float2* xb   = x + b;
    float*        spk  = out + b;
    float*        memo = out + (size_t)T_STEPS * BATCH + b;

    float mem = 0.0f;
    float inh = 0.0f;

    // Prologue: prefetch windows t0 and t0+U.
    float2 buf0[U], buf1[U];
    if (chunk == 0) {
#pragma unroll
        for (int u = 0; u < U; u++)
            buf0[u] = __ldcs(xb + (size_t)(t0 + u) * STRIDE);
#pragma unroll
        for (int u = 0; u < U; u++)
            buf1[u] = __ldcs(xb + (size_t)(t0 + U + u) * STRIDE);
    } else {
#pragma unroll
        for (int u = 0; u < U; u++)
            buf0[u] = ldg_keep(xb + (size_t)(t0 + u) * STRIDE, pol);
#pragma unroll
        for (int u = 0; u < U; u++)
            buf1[u] = ldg_keep(xb + (size_t)(t0 + U + u) * STRIDE, pol);
    }

    int t = t0;
    // Warm-up: advance state, no stores, evict_last loads (first reader of
    // data the trailing chunk's main loop re-reads). Empty for chunk 0.
    for (; t < cs; t += 2 * U) {
        win<false, true, true>(buf0, xb + (size_t)(t + 2 * U) * STRIDE, pol,
                               mem, inh, w0, w1, wi, spk, memo, t);
        win<false, true, true>(buf1, xb + (size_t)(t + 3 * U) * STRIDE, pol,
                               mem, inh, w0, w1, wi, spk, memo, t + U);
    }
    // Main stored region: streaming loads (we are the last reader).
    for (; t < ce - 2 * U; t += 2 * U) {
        win<true, true, false>(buf0, xb + (size_t)(t + 2 * U) * STRIDE, pol,
                               mem, inh, w0, w1, wi, spk, memo, t);
        win<true, true, false>(buf1, xb + (size_t)(t + 3 * U) * STRIDE, pol,
                               mem, inh, w0, w1, wi, spk, memo, t + U);
    }
    // Epilogue: last two windows.
    win<true, false, false>(buf0, nullptr, pol, mem, inh, w0, w1, wi, spk, memo, t);
    win<true, false, false>(buf1, nullptr, pol, mem, inh, w0, w1, wi, spk, memo, t + U);
}

extern "C" void kernel_launch(void* const* d_in, const int* in_sizes, int n_in,
                              void* d_out, int out_size) {
    const float* x     = (const float*)d_in[0];  // spike_seq [1024,16384,2]
    const float* w_exc = (const float*)d_in[1];  // [1,2]
    const float* w_inh = (const float*)d_in[2];  // scalar
    float* out = (float*)d_out;                  // [2,1024,16384]

    fmfm_kernel<<<(BATCH / TPB) * NCHUNK, TPB>>>((const float2*)x, w_exc, w_inh, out);
}

// round 9
// speedup vs baseline: 1.0292x; 1.0292x over previous
#include <cuda_runtime.h>

// FMFMNeuronInhib: T=1024 LIF steps over B=16384 neurons. HBM stream.
// R9: R7 algorithm verbatim (4 balanced chunks of 400 steps, WARM=192,
// depth-2 U=8 register prefetch, evict_last policy on warm-up loads,
// streaming main loads/stores), TPB 128->64. Rationale: R7's 512 blocks
// quantize 3.46 blocks/SM -> 68 SMs carry 4 blocks while 80 carry 3
// (+15.6% straggler tail; R8's 256-block grid had the same 2-vs-1 split
// and confirmed it). 1024 blocks of 64 threads quantize 7-vs-6 (+1.2%),
// all resident in one wave (regs ~120 -> 8 blocks/SM cap).

#define T_STEPS 1024
#define BATCH   16384
#define NCHUNK  4
#define WARM    192
#define L_TAIL  208                                  // stored, chunks 1..3
#define L_HEAD  (T_STEPS - (NCHUNK - 1) * L_TAIL)    // 400, chunk 0
#define U       8
#define TPB     64
#define STRIDE  ((size_t)BATCH)

// evict_last access policy (fraction 1.0)
__device__ __forceinline__ unsigned long long make_keep_policy() {
    unsigned long long pol;
    asm("createpolicy.fractional.L2::evict_last.b64 %0, 1.0;" : "=l"(pol));
    return pol;
}

// First-of-two-readers load: keep in L2 until the trailing reader arrives.
__device__ __forceinline__ float2 ldg_keep(const float2* p, unsigned long long pol) {
    float2 v;
    asm("ld.global.nc.L2::cache_hint.v2.f32 {%0,%1}, [%2], %3;"
        : "=f"(v.x), "=f"(v.y) : "l"(p), "l"(pol));
    return v;
}

template <bool STORE, bool PREFETCH, bool KEEP>
__device__ __forceinline__ void win(
    float2* __restrict__ buf,        // consumed; refilled from `pre` if PREFETCH
    const float2* __restrict__ pre,  // absolute src of window t+2U
    unsigned long long pol,
    float& mem, float& inh,
    float w0, float w1, float wi,
    float* __restrict__ spk, float* __restrict__ memo, int tbase)
{
#pragma unroll
    for (int u = 0; u < U; u++) {
        const float2 v = buf[u];
        if (PREFETCH)
            buf[u] = KEEP ? ldg_keep(pre + (size_t)u * STRIDE, pol)
                          : __ldcs(pre + (size_t)u * STRIDE);

        // inh = 0.6*inh + x0
        inh = fmaf(0.6f, inh, v.x);
        // cur = 0.7*x0 + 1.0*x1 + w_inh*inh
        float cur = fmaf(w0, v.x, w1 * v.y);
        cur = fmaf(wi, inh, cur);
        // reset from OLD mem (threshold 1), then mem = 0.9*mem + cur - reset
        const float reset = (mem > 1.0f) ? 1.0f : 0.0f;
        mem = fmaf(0.9f, mem, cur - reset);

        if (STORE) {
            const float s = (mem > 1.0f) ? 1.0f : 0.0f;
            __stcs(spk  + (size_t)(tbase + u) * STRIDE, s);
            __stcs(memo + (size_t)(tbase + u) * STRIDE, mem);
        }
    }
}

__global__ void __launch_bounds__(TPB, 1) fmfm_kernel(
    const float2* __restrict__ x,      // [T, B] pairs (x0, x1)
    const float*  __restrict__ w_exc,  // [2] = {0.7, 1.0}
    const float*  __restrict__ w_inh,  // [1] = {-1.0}
    float*        __restrict__ out)    // [2, T, B]: spk_rec then mem_rec
{
    const int nb    = BATCH / TPB;                 // blocks per chunk
    const int chunk = blockIdx.x / nb;
    const int b     = (blockIdx.x % nb) * TPB + threadIdx.x;

    const float w0 = __ldg(&w_exc[0]);
    const float w1 = __ldg(&w_exc[1]);
    const float wi = __ldg(&w_inh[0]);

    const unsigned long long pol = make_keep_policy();

    // Chunk 0: store [0, 400), no warm-up (400 steps total).
    // Chunk i>=1: store [400 + (i-1)*208, +208), warm-up 192 (400 steps total).
    const int cs = (chunk == 0) ? 0 : L_HEAD + (chunk - 1) * L_TAIL;
    const int ce = (chunk == 0) ? L_HEAD : cs + L_TAIL;
    const int t0 = (chunk == 0) ? 0 : cs - WARM;

    const float2* xb   = x + b;
    float*        spk  = out + b;
    float*        memo = out + (size_t)T_STEPS * BATCH + b;

    float mem = 0.0f;
    float inh = 0.0f;

    // Prologue: prefetch windows t0 and t0+U.
    float2 buf0[U], buf1[U];
    if (chunk == 0) {
#pragma unroll
        for (int u = 0; u < U; u++)
            buf0[u] = __ldcs(xb + (size_t)(t0 + u) * STRIDE);
#pragma unroll
        for (int u = 0; u < U; u++)
            buf1[u] = __ldcs(xb + (size_t)(t0 + U + u) * STRIDE);
    } else {
#pragma unroll
        for (int u = 0; u < U; u++)
            buf0[u] = ldg_keep(xb + (size_t)(t0 + u) * STRIDE, pol);
#pragma unroll
        for (int u = 0; u < U; u++)
            buf1[u] = ldg_keep(xb + (size_t)(t0 + U + u) * STRIDE, pol);
    }

    int t = t0;
    // Warm-up: advance state, no stores, evict_last loads (first reader of
    // data the trailing chunk's main loop re-reads). Empty for chunk 0.
    for (; t < cs; t += 2 * U) {
        win<false, true, true>(buf0, xb + (size_t)(t + 2 * U) * STRIDE, pol,
                               mem, inh, w0, w1, wi, spk, memo, t);
        win<false, true, true>(buf1, xb + (size_t)(t + 3 * U) * STRIDE, pol,
                               mem, inh, w0, w1, wi, spk, memo, t + U);
    }
    // Main stored region: streaming loads (we are the last reader).
    for (; t < ce - 2 * U; t += 2 * U) {
        win<true, true, false>(buf0, xb + (size_t)(t + 2 * U) * STRIDE, pol,
                               mem, inh, w0, w1, wi, spk, memo, t);
        win<true, true, false>(buf1, xb + (size_t)(t + 3 * U) * STRIDE, pol,
                               mem, inh, w0, w1, wi, spk, memo, t + U);
    }
    // Epilogue: last two windows.
    win<true, false, false>(buf0, nullptr, pol, mem, inh, w0, w1, wi, spk, memo, t);
    win<true, false, false>(buf1, nullptr, pol, mem, inh, w0, w1, wi, spk, memo, t + U);
}

extern "C" void kernel_launch(void* const* d_in, const int* in_sizes, int n_in,
                              void* d_out, int out_size) {
    const float* x     = (const float*)d_in[0];  // spike_seq [1024,16384,2]
    const float* w_exc = (const float*)d_in[1];  // [1,2]
    const float* w_inh = (const float*)d_in[2];  // scalar
    float* out = (float*)d_out;                  // [2,1024,16384]

    fmfm_kernel<<<(BATCH / TPB) * NCHUNK, TPB>>>((const float2*)x, w_exc, w_inh, out);
}